// round 15
// baseline (speedup 1.0000x reference)
#include <cuda_runtime.h>
#include <cstdint>

#define N_FFT 8192
#define NT    512
#define D_CH  512
#define SEQ   4096

#define PADI(i) ((i) + ((i) >> 4))
#define BUFSZ (N_FFT + (N_FFT >> 4))   // 8704 float2 = 69632 B

// Block ranges in the fused kernel
#define B_TT   0
#define B_XP   1024
#define B_TF   2048
#define B_CV   2304
#define B_OP   3328
#define B_END  4352

// Sync state: [0,8) cntT, [8,24) cntX, [24,40) cntC, [40,296) fT flags
#define SY_CNTT 0
#define SY_CNTX 8
#define SY_CNTC 24
#define SY_FT   40
__device__ int    g_sync[296];

__device__ float2 g_tw[N_FFT];
__device__ float4 g_tfft[(size_t)D_CH * SEQ];        // [d][q] = (T[q], T[q+4096])
__device__ float2 g_xP[(size_t)2 * D_CH * SEQ];      // [pair][d][n]
__device__ float  g_tT[(size_t)D_CH * 2 * SEQ];
__device__ float2 g_oP[(size_t)2 * D_CH * SEQ];

__device__ __forceinline__ float2 cadd(float2 a, float2 b) { return make_float2(a.x + b.x, a.y + b.y); }
__device__ __forceinline__ float2 csub(float2 a, float2 b) { return make_float2(a.x - b.x, a.y - b.y); }
__device__ __forceinline__ float2 cmul(float2 a, float2 b) {
    return make_float2(a.x * b.x - a.y * b.y, a.x * b.y + a.y * b.x);
}
template <bool INV>
__device__ __forceinline__ float2 mulJ(float2 z) {
    return INV ? make_float2(-z.y, z.x) : make_float2(z.y, -z.x);
}
template <bool INV>
__device__ __forceinline__ float2 twc(float2 z, float re, float im) {
    float2 w = make_float2(re, INV ? -im : im);
    return cmul(z, w);
}

template <bool INV>
__device__ __forceinline__ void dft4(float2& a0, float2& a1, float2& a2, float2& a3) {
    float2 t0 = cadd(a0, a2), t1 = csub(a0, a2);
    float2 t2 = cadd(a1, a3), t3 = mulJ<INV>(csub(a1, a3));
    a0 = cadd(t0, t2);
    a1 = cadd(t1, t3);
    a2 = csub(t0, t2);
    a3 = csub(t1, t3);
}

template <bool INV>
__device__ __forceinline__ void dft16(float2 a[16]) {
    const float C1 = 0.92387953251128675613f;
    const float S1 = 0.38268343236508977173f;
    const float H  = 0.70710678118654752440f;
#pragma unroll
    for (int ji = 0; ji < 4; ji++) dft4<INV>(a[ji], a[ji + 4], a[ji + 8], a[ji + 12]);
    a[5]  = twc<INV>(a[5],  C1, -S1);
    a[9]  = twc<INV>(a[9],   H,  -H);
    a[13] = twc<INV>(a[13], S1, -C1);
    a[6]  = twc<INV>(a[6],   H,  -H);
    a[10] = mulJ<INV>(a[10]);
    a[14] = twc<INV>(a[14], -H,  -H);
    a[7]  = twc<INV>(a[7],  S1, -C1);
    a[11] = twc<INV>(a[11], -H,  -H);
    a[15] = twc<INV>(a[15], -C1, S1);
#pragma unroll
    for (int ro = 0; ro < 4; ro++) dft4<INV>(a[4 * ro], a[4 * ro + 1], a[4 * ro + 2], a[4 * ro + 3]);
}

template <bool INV>
__device__ __forceinline__ void tw_load(int sLog, int tid, float2& w1, float2& w8) {
    const int tb = (tid >> sLog) << sLog;
    w1 = g_tw[tb];
    w8 = g_tw[tb << 3];
    if (INV) { w1.y = -w1.y; w8.y = -w8.y; }
}

__device__ __forceinline__ void pass16_write(float2* __restrict__ X, const float2 a[16],
                                             int sLog, int tid, float2 w1, float2 w8) {
    constexpr int SW16[16] = {0,4,8,12, 1,5,9,13, 2,6,10,14, 3,7,11,15};
    const int q = tid & ((1 << sLog) - 1);
    const int p = tid >> sLog;
    const int ob = q + (p << (sLog + 4));
    X[PADI(ob)] = a[SW16[0]];
    float2 w = w1;
#pragma unroll
    for (int r = 1; r < 8; r++) {
        X[PADI(ob + (r << sLog))] = cmul(a[SW16[r]], w);
        w = cmul(w, w1);
    }
    X[PADI(ob + (8 << sLog))] = cmul(a[SW16[8]], w8);
    w = cmul(w8, w1);
#pragma unroll
    for (int r = 9; r < 16; r++) {
        X[PADI(ob + (r << sLog))] = cmul(a[SW16[r]], w);
        w = cmul(w, w1);
    }
}

template <bool INV>
__device__ __forceinline__ void pass16(float2* __restrict__ X, int sLog, int tid) {
    float2 a[16];
#pragma unroll
    for (int r = 0; r < 16; r++) a[r] = X[PADI(tid + 512 * r)];
    dft16<INV>(a);
    float2 w1, w8;
    tw_load<INV>(sLog, tid, w1, w8);
    __syncthreads();
    pass16_write(X, a, sLog, tid, w1, w8);
    __syncthreads();
}

// 64x64 float4 transpose tile (512 threads): I is RxC, O is CxR.
__device__ __forceinline__ void t4_tile512(const float* __restrict__ I, float* __restrict__ O,
                                           int R, int C, int r0, int c0, float* tile, int tid) {
#pragma unroll
    for (int k = 0; k < 2; k++) {
        int idx = k * 512 + tid;
        int row = idx >> 4, c4 = idx & 15;
        float4 v = *reinterpret_cast<const float4*>(I + (size_t)(r0 + row) * C + c0 + 4 * c4);
        tile[row * 65 + 4 * c4 + 0] = v.x;
        tile[row * 65 + 4 * c4 + 1] = v.y;
        tile[row * 65 + 4 * c4 + 2] = v.z;
        tile[row * 65 + 4 * c4 + 3] = v.w;
    }
    __syncthreads();
#pragma unroll
    for (int k = 0; k < 2; k++) {
        int idx = k * 512 + tid;
        int c = idx >> 4, r4 = idx & 15;
        float4 v = make_float4(tile[(4 * r4 + 0) * 65 + c], tile[(4 * r4 + 1) * 65 + c],
                               tile[(4 * r4 + 2) * 65 + c], tile[(4 * r4 + 3) * 65 + c]);
        *reinterpret_cast<float4*>(O + (size_t)(c0 + c) * R + r0 + 4 * r4) = v;
    }
}

// x pair-transpose tile (512 threads)
__device__ __forceinline__ void xP_tile(const float* __restrict__ xb0, const float* __restrict__ xb1,
                                        float2* __restrict__ outP, int n0, int d0,
                                        float* t0, float* t1, int tid) {
#pragma unroll
    for (int k = 0; k < 2; k++) {
        int idx = k * 512 + tid;
        int n = idx >> 4, c4 = idx & 15;
        float4 v0 = *reinterpret_cast<const float4*>(xb0 + (size_t)(n0 + n) * D_CH + d0 + 4 * c4);
        float4 v1 = *reinterpret_cast<const float4*>(xb1 + (size_t)(n0 + n) * D_CH + d0 + 4 * c4);
        t0[n * 65 + 4 * c4 + 0] = v0.x; t0[n * 65 + 4 * c4 + 1] = v0.y;
        t0[n * 65 + 4 * c4 + 2] = v0.z; t0[n * 65 + 4 * c4 + 3] = v0.w;
        t1[n * 65 + 4 * c4 + 0] = v1.x; t1[n * 65 + 4 * c4 + 1] = v1.y;
        t1[n * 65 + 4 * c4 + 2] = v1.z; t1[n * 65 + 4 * c4 + 3] = v1.w;
    }
    __syncthreads();
#pragma unroll
    for (int k = 0; k < 4; k++) {
        int idx = k * 512 + tid;
        int c = idx >> 5, g = idx & 31;
        float4 w = make_float4(t0[(2 * g) * 65 + c], t1[(2 * g) * 65 + c],
                               t0[(2 * g + 1) * 65 + c], t1[(2 * g + 1) * 65 + c]);
        *reinterpret_cast<float4*>(outP + (size_t)(d0 + c) * SEQ + n0 + 2 * g) = w;
    }
}

// o pair-detranspose tile (512 threads); __ldcg: data produced by other blocks this launch.
__device__ __forceinline__ void oP_tile(const float2* __restrict__ inP,
                                        float* __restrict__ ob0, float* __restrict__ ob1,
                                        int n0, int d0, float* t0, float* t1, int tid) {
#pragma unroll
    for (int k = 0; k < 4; k++) {
        int idx = k * 512 + tid;
        int c = idx >> 5, g = idx & 31;
        float4 v = __ldcg(reinterpret_cast<const float4*>(inP + (size_t)(d0 + c) * SEQ + n0 + 2 * g));
        t0[c * 65 + 2 * g]     = v.x;  t1[c * 65 + 2 * g]     = v.y;
        t0[c * 65 + 2 * g + 1] = v.z;  t1[c * 65 + 2 * g + 1] = v.w;
    }
    __syncthreads();
#pragma unroll
    for (int k = 0; k < 2; k++) {
        int idx = k * 512 + tid;
        int n = idx >> 4, d4 = idx & 15;
        float4 w0 = make_float4(t0[(4 * d4 + 0) * 65 + n], t0[(4 * d4 + 1) * 65 + n],
                                t0[(4 * d4 + 2) * 65 + n], t0[(4 * d4 + 3) * 65 + n]);
        float4 w1 = make_float4(t1[(4 * d4 + 0) * 65 + n], t1[(4 * d4 + 1) * 65 + n],
                                t1[(4 * d4 + 2) * 65 + n], t1[(4 * d4 + 3) * 65 + n]);
        *reinterpret_cast<float4*>(ob0 + (size_t)(n0 + n) * D_CH + d0 + 4 * d4) = w0;
        *reinterpret_cast<float4*>(ob1 + (size_t)(n0 + n) * D_CH + d0 + 4 * d4) = w1;
    }
}

// Conv body for one (pr, d) unit.
__device__ __forceinline__ void conv_body(float2* __restrict__ X, int pr, int d, int tid) {
    const float2* xp = g_xP + ((size_t)pr * D_CH + d) * SEQ;
    {
        float2 a[16];
#pragma unroll
        for (int r = 0; r < 8; r++) a[r] = xp[tid + 512 * r];
#pragma unroll
        for (int r = 8; r < 16; r++) a[r] = make_float2(0.0f, 0.0f);
        dft16<false>(a);
        float2 w1, w8;
        tw_load<false>(0, tid, w1, w8);
        pass16_write(X, a, 0, tid, w1, w8);
        __syncthreads();
    }
    pass16<false>(X, 4, tid);
    pass16<false>(X, 8, tid);
    {
        const float4* tf = g_tfft + (size_t)d * SEQ;
        const float inv = 1.0f / (float)N_FFT;
        float2 a[16];
#pragma unroll
        for (int i = 0; i < 8; i++) {
            int q = tid + 512 * i;
            float4 w = tf[q];
            float2 u = X[PADI(q)];
            float2 v = X[PADI(q + 4096)];
            float2 s = cmul(cadd(u, v), make_float2(w.x, w.y));
            float2 dd = cmul(csub(u, v), make_float2(w.z, w.w));
            a[i]     = make_float2(s.x * inv, s.y * inv);
            a[i + 8] = make_float2(dd.x * inv, dd.y * inv);
        }
        dft16<true>(a);
        float2 w1, w8;
        tw_load<true>(0, tid, w1, w8);
        __syncthreads();
        pass16_write(X, a, 0, tid, w1, w8);
        __syncthreads();
    }
    pass16<true>(X, 4, tid);
    pass16<true>(X, 8, tid);

    float2* op = g_oP + ((size_t)pr * D_CH + d) * SEQ;
#pragma unroll
    for (int i = 0; i < 8; i++) {
        int q = tid + 512 * i;
        op[q] = cadd(X[PADI(q)], X[PADI(q + 4096)]);
    }
}

// ---------------------------------------------------------------------------
// The whole pipeline as one kernel; dependencies enforced by counters/flags.
// Producers have lower block ids than their consumers -> dispatch order makes
// the spin-waits deadlock-free.
__global__ void __launch_bounds__(NT, 2) ker_all(const float* __restrict__ x,
                                                 const float* __restrict__ t,
                                                 float* __restrict__ o) {
    extern __shared__ float2 sm[];
    const int tid = threadIdx.x;
    const int bid = blockIdx.x;
    volatile int* sy = g_sync;

    if (bid < B_XP) {
        // ---- t transpose tile (+ redundant g_tw fill so each d-group implies full table) ----
        const int tt = bid;                    // 0..1023
        const int dg = tt & 7;
        const int rt = tt >> 3;                // 0..127
        if (tid < 64) {
            int k = rt * 64 + tid;
            float s, c;
            sincospif(-2.0f * (float)k / (float)N_FFT, &s, &c);
            g_tw[k] = make_float2(c, s);
        }
        t4_tile512(t, g_tT, 2 * SEQ, D_CH, rt * 64, dg * 64,
                   reinterpret_cast<float*>(sm), tid);
        __threadfence();
        __syncthreads();
        if (tid == 0) atomicAdd(&g_sync[SY_CNTT + dg], 1);
        return;
    }

    if (bid < B_TF) {
        // ---- x pair-transpose tile ----
        const int tt = bid - B_XP;             // 0..1023
        const int p = tt >> 9;
        const int rem = tt & 511;
        const int dg = rem & 7;
        const int d0 = dg * 64;
        const int n0 = (rem >> 3) * 64;
        const float* xb0 = x + (size_t)(2 * p) * SEQ * D_CH;
        const float* xb1 = xb0 + (size_t)SEQ * D_CH;
        float* t0 = reinterpret_cast<float*>(sm);
        float* t1 = t0 + 64 * 65;
        xP_tile(xb0, xb1, g_xP + (size_t)p * D_CH * SEQ, n0, d0, t0, t1, tid);
        __threadfence();
        __syncthreads();
        if (tid == 0) atomicAdd(&g_sync[SY_CNTX + p * 8 + dg], 1);
        return;
    }

    if (bid < B_CV) {
        // ---- tfft: channels (2c0, 2c0+1); waits for its tT d-group ----
        const int c0 = bid - B_TF;             // 0..255
        if (tid == 0) {
            while (sy[SY_CNTT + (c0 >> 5)] < 128) __nanosleep(200);
        }
        __syncthreads();
        __threadfence();
        float2* X = sm;
        const float* t0 = g_tT + (size_t)(2 * c0) * N_FFT;
        const float* t1 = t0 + N_FFT;
        {
            float2 a[16];
#pragma unroll
            for (int r = 0; r < 16; r++)
                a[r] = make_float2(t0[tid + 512 * r], t1[tid + 512 * r]);
            dft16<false>(a);
            float2 w1, w8;
            tw_load<false>(0, tid, w1, w8);
            pass16_write(X, a, 0, tid, w1, w8);
            __syncthreads();
        }
        pass16<false>(X, 4, tid);
        pass16<false>(X, 8, tid);

        float4* out0 = g_tfft + (size_t)(2 * c0) * SEQ;
        float4* out1 = out0 + SEQ;
#pragma unroll
        for (int i = 0; i < 8; i++) {
            int k = tid + 512 * i;
            float2 ua = X[PADI(k)], ub = X[PADI(k + 4096)];
            float2 Zk  = cadd(ua, ub);
            float2 Zk2 = csub(ua, ub);
            int m = (4096 - k) & 4095;
            float2 va = X[PADI(m)], vb = X[PADI(m + 4096)];
            bool kz = (k == 0);
            float2 Zn  = kz ? cadd(va, vb) : csub(va, vb);
            float2 Zn2 = kz ? csub(va, vb) : cadd(va, vb);
            out0[k] = make_float4(0.5f * (Zk.x + Zn.x),  0.5f * (Zk.y - Zn.y),
                                  0.5f * (Zk2.x + Zn2.x), 0.5f * (Zk2.y - Zn2.y));
            out1[k] = make_float4(0.5f * (Zk.y + Zn.y),  -0.5f * (Zk.x - Zn.x),
                                  0.5f * (Zk2.y + Zn2.y), -0.5f * (Zk2.x - Zn2.x));
        }
        __threadfence();
        __syncthreads();
        if (tid == 0) atomicExch(&g_sync[SY_FT + c0], 1);
        return;
    }

    if (bid < B_OP) {
        // ---- conv: waits for its channel's tfft flag and its xP group ----
        const int cv = bid - B_CV;             // 0..1023
        const int pr = cv >> 9;
        const int d = cv & (D_CH - 1);
        if (tid == 0) {
            while (sy[SY_FT + (d >> 1)] == 0) __nanosleep(200);
            while (sy[SY_CNTX + pr * 8 + (d >> 6)] < 64) __nanosleep(200);
        }
        __syncthreads();
        __threadfence();
        conv_body(sm, pr, d, tid);
        __threadfence();
        __syncthreads();
        if (tid == 0) atomicAdd(&g_sync[SY_CNTC + pr * 8 + (d >> 6)], 1);
        return;
    }

    // ---- o pair-detranspose: waits for its conv group ----
    const int tt = bid - B_OP;                 // 0..1023
    const int p = tt >> 9;
    const int rem = tt & 511;
    const int dg = rem & 7;
    const int d0 = dg * 64;
    const int n0 = (rem >> 3) * 64;
    if (tid == 0) {
        while (sy[SY_CNTC + p * 8 + dg] < 64) __nanosleep(200);
    }
    __syncthreads();
    __threadfence();
    float* t0 = reinterpret_cast<float*>(sm);
    float* t1 = t0 + 64 * 65;
    float* ob0 = o + (size_t)(2 * p) * SEQ * D_CH;
    float* ob1 = ob0 + (size_t)SEQ * D_CH;
    oP_tile(g_oP + (size_t)p * D_CH * SEQ, ob0, ob1, n0, d0, t0, t1, tid);
}

extern "C" void kernel_launch(void* const* d_in, const int* in_sizes, int n_in,
                              void* d_out, int out_size) {
    const float* x = (const float*)d_in[0];
    const float* t = (const float*)d_in[1];
    if (n_in >= 2 && in_sizes[0] < in_sizes[1]) {
        const float* tmp = x; x = t; t = tmp;
    }
    float* o = (float*)d_out;

    void* syncAddr;
    cudaGetSymbolAddress(&syncAddr, g_sync);
    cudaMemsetAsync(syncAddr, 0, sizeof(int) * 296);

    const size_t smem = (size_t)BUFSZ * sizeof(float2);  // 69632 B -> 2 blocks/SM
    cudaFuncSetAttribute(ker_all, cudaFuncAttributeMaxDynamicSharedMemorySize, (int)smem);

    ker_all<<<B_END, NT, smem>>>(x, t, o);
}